// round 2
// baseline (speedup 1.0000x reference)
#include <cuda_runtime.h>
#include <cuda_bf16.h>

// TIME_WARPING: per-row not-a-knot cubic spline fit + warped evaluation.
//
// Math: the (1,4,1) spline tridiagonal with not-a-knot ends reduces to
//   M1 = rhs1/6, M_{S-2} = rhs_{S-2}/6  (exact, from row elimination)
//   interior: tri(1,4,1) u = r'   with Dirichlet virtual zeros at 1, S-2
// solved by causal+anticausal first-order IIR with lambda = sqrt(3)-2
// (root of l^2+4l+1=0):  p_k = r_k + l*p_{k-1};  q_k = p_k + l*q_{k+1};
// u = -l*q.  Each thread solves a 32-chunk with W=12 warm-up steps
// (error |l|^12 ~ 1.4e-7, far below the 1e-3 tolerance). Boundaries
// handled exactly via method-of-images in rprime().

#define S      4096
#define NT     128
#define CHUNK  32      // NT * CHUNK == S
#define W      12      // IIR warm-up length
#define PSTR   131     // permuted shared layout inner stride (odd, mod32=3)
#define PERM(i) ((((i) & 31) * PSTR) + ((i) >> 5))

__device__ __forceinline__ float rp_raw(const float* sx, int j) {
    // rhs_j = 6*(x[j-1] - 2x[j] + x[j+1]), valid for 1 <= j <= S-2
    return 6.f * (sx[PERM(j - 1)] - 2.f * sx[PERM(j)] + sx[PERM(j + 1)]);
}

// Extended (image) RHS for the Dirichlet interior system. Valid for
// j in [-W-1, S-1+W+1]. Images: Dirichlet at node 1 and node S-2.
__device__ __forceinline__ float rprime(const float* sx, int j, float M1, float MS2) {
    if (j >= 2 && j <= S - 3) {
        float v = rp_raw(sx, j);
        if (j == 2)     v -= M1;
        if (j == S - 3) v -= MS2;
        return v;
    }
    if (j == 1 || j == S - 2) return 0.f;
    if (j <= 0) {
        int m = 2 - j;              // in [2, W+2]
        float v = rp_raw(sx, m);
        if (m == 2) v -= M1;
        return -v;
    }
    int m = 2 * (S - 2) - j;        // j >= S-1  ->  m in [S-3-W, S-3]
    float v = rp_raw(sx, m);
    if (m == S - 3) v -= MS2;
    return -v;
}

__global__ __launch_bounds__(NT)
void tw_kernel(const float* __restrict__ x,
               const float* __restrict__ scale,
               const int* __restrict__ mask,
               float* __restrict__ out, int C)
{
    __shared__ float sx[32 * PSTR];   // x row, permuted layout
    __shared__ float sm[32 * PSTR];   // M row, permuted layout

    const int c   = blockIdx.x;
    const int b   = blockIdx.y;
    const int tid = threadIdx.x;
    const size_t row = ((size_t)b * C + c) * (size_t)S;
    const float* xr   = x + row;
    float*       orow = out + row;

    // Per-sample apply decision (uniform across the block -> no divergence).
    const bool apply = (mask[b] != 0);
    if (!apply) {
        const float4* xi = (const float4*)xr;
        float4*       oo = (float4*)orow;
        #pragma unroll
        for (int g = 0; g < S / 4 / NT; ++g)
            oo[g * NT + tid] = xi[g * NT + tid];
        return;
    }

    const float scl = scale[b];

    // ---- stage x into shared (permuted; scalar loads are fully coalesced,
    //      scalar stores hit banks at stride 3 -> conflict-free) ----
    #pragma unroll
    for (int g = 0; g < S / NT; ++g) {
        int i = g * NT + tid;
        sx[PERM(i)] = xr[i];
    }
    __syncthreads();

    // ---- spline second derivatives M via chunked two-pass IIR ----
    const float LAM = -0.26794919243112270647f;  // sqrt(3) - 2
    const float PL  =  0.26794919243112270647f;  // -LAM

    const int i0 = tid * CHUNK;
    float pv[CHUNK + W];

    // Fast path: all RHS reads are plain interior values (threads 1..126).
    const bool fastpath = (i0 >= W + 3) && (i0 + CHUNK - 1 + W <= S - 4);

    if (fastpath) {
        float xm = sx[PERM(i0 - W - 1)];
        float xc = sx[PERM(i0 - W)];
        float p  = 0.f;
        #pragma unroll
        for (int k = 0; k < CHUNK + 2 * W; ++k) {
            float xp = sx[PERM(i0 - W + k + 1)];
            float r  = 6.f * (xm - 2.f * xc + xp);
            p = fmaf(LAM, p, r);
            if (k >= W) pv[k - W] = p;
            xm = xc; xc = xp;
        }
    } else {
        const float M1  = sx[PERM(0)]     - 2.f * sx[PERM(1)]     + sx[PERM(2)];
        const float MS2 = sx[PERM(S - 3)] - 2.f * sx[PERM(S - 2)] + sx[PERM(S - 1)];
        float p = 0.f;
        #pragma unroll
        for (int k = 0; k < CHUNK + 2 * W; ++k) {
            float r = rprime(sx, i0 - W + k, M1, MS2);
            p = fmaf(LAM, p, r);
            if (k >= W) pv[k - W] = p;
        }
    }

    // Backward (anticausal) pass, entirely in registers; write M to shared.
    {
        float q = 0.f;
        #pragma unroll
        for (int k = CHUNK + W - 1; k >= 0; --k) {
            q = fmaf(LAM, q, pv[k]);
            if (k < CHUNK) sm[PERM(i0 + k)] = PL * q;
        }
    }

    // Exact boundary M values (same-thread read-after-write on own chunk).
    if (tid == 0) {
        float M1 = sx[PERM(0)] - 2.f * sx[PERM(1)] + sx[PERM(2)];
        sm[PERM(1)] = M1;
        sm[PERM(0)] = 2.f * M1 - sm[PERM(2)];
    }
    if (tid == NT - 1) {
        float MS2 = sx[PERM(S - 3)] - 2.f * sx[PERM(S - 2)] + sx[PERM(S - 1)];
        sm[PERM(S - 2)] = MS2;
        sm[PERM(S - 1)] = 2.f * MS2 - sm[PERM(S - 3)];
    }
    __syncthreads();

    // ---- warped cubic evaluation, coalesced float4 stores ----
    #pragma unroll
    for (int g = 0; g < S / 4 / NT; ++g) {
        const int v  = g * NT + tid;
        const int s0 = v * 4;
        float4 o;
        float* op = (float*)&o;
        #pragma unroll
        for (int e = 0; e < 4; ++e) {
            float wv = fminf((float)(s0 + e) * scl, (float)(S - 1));
            int idx = (int)wv;            // wv >= 0 -> trunc == floor
            if (idx > S - 2) idx = S - 2;
            float tt = wv - (float)idx;
            float y0 = sx[PERM(idx)];
            float y1 = sx[PERM(idx + 1)];
            float m0 = sm[PERM(idx)];
            float m1 = sm[PERM(idx + 1)];
            float bb = (y1 - y0) - (2.f * m0 + m1) * (1.f / 6.f);
            float cc = 0.5f * m0;
            float dd = (m1 - m0) * (1.f / 6.f);
            op[e] = fmaf(tt, fmaf(tt, fmaf(tt, dd, cc), bb), y0);
        }
        ((float4*)orow)[v] = o;
    }
}

extern "C" void kernel_launch(void* const* d_in, const int* in_sizes, int n_in,
                              void* d_out, int out_size)
{
    const float* x     = (const float*)d_in[0];
    const float* scale = (const float*)d_in[1];
    const int*   mask  = (const int*)d_in[2];
    float*       out   = (float*)d_out;

    const int B = in_sizes[1];                 // 128
    const int C = in_sizes[0] / (B * S);       // 64

    dim3 grid(C, B);
    tw_kernel<<<grid, NT>>>(x, scale, mask, out, C);
}

// round 6
// speedup vs baseline: 1.0293x; 1.0293x over previous
#include <cuda_runtime.h>
#include <cuda_bf16.h>

// TIME_WARPING: per-row not-a-knot cubic spline fit + warped evaluation.
//
// Math: the (1,4,1) spline tridiagonal with not-a-knot ends reduces to
//   M1 = rhs1/6, M_{S-2} = rhs_{S-2}/6  (exact, from row elimination)
//   interior: tri(1,4,1) u = r'   with Dirichlet virtual zeros at 1, S-2
// solved by causal+anticausal first-order IIR with lambda = sqrt(3)-2
// (root of l^2+4l+1=0):  p_k = r_k + l*p_{k-1};  q_k = p_k + l*q_{k+1};
// u = -l*q.  Each thread solves a 16-chunk with W=8 warm-up steps
// (error |l|^8 ~ 2.7e-5, far below the 1e-3 tolerance). Boundaries
// handled exactly via method-of-images in rprime().

#define S      4096
#define NT     256
#define CHUNK  16      // NT * CHUNK == S
#define W      8       // IIR warm-up length
#define PSTR   131     // permuted shared layout inner stride (odd, mod32=3)
#define PERM(i) ((((i) & 31) * PSTR) + ((i) >> 5))

__device__ __forceinline__ float rp_raw(const float* sx, int j) {
    // rhs_j = 6*(x[j-1] - 2x[j] + x[j+1]), valid for 1 <= j <= S-2
    return 6.f * (sx[PERM(j - 1)] - 2.f * sx[PERM(j)] + sx[PERM(j + 1)]);
}

// Extended (image) RHS for the Dirichlet interior system. Valid for
// j in [-W-1, S-1+W+1]. Images: Dirichlet at node 1 and node S-2.
__device__ __forceinline__ float rprime(const float* sx, int j, float M1, float MS2) {
    if (j >= 2 && j <= S - 3) {
        float v = rp_raw(sx, j);
        if (j == 2)     v -= M1;
        if (j == S - 3) v -= MS2;
        return v;
    }
    if (j == 1 || j == S - 2) return 0.f;
    if (j <= 0) {
        int m = 2 - j;              // in [2, W+2]
        float v = rp_raw(sx, m);
        if (m == 2) v -= M1;
        return -v;
    }
    int m = 2 * (S - 2) - j;        // j >= S-1  ->  m in [S-3-W, S-3]
    float v = rp_raw(sx, m);
    if (m == S - 3) v -= MS2;
    return -v;
}

__global__ __launch_bounds__(NT)
void tw_kernel(const float* __restrict__ x,
               const float* __restrict__ scale,
               const int* __restrict__ mask,
               float* __restrict__ out, int C)
{
    __shared__ float sx[32 * PSTR];   // x row, permuted layout
    __shared__ float sm[32 * PSTR];   // M row, permuted layout

    const int c   = blockIdx.x;
    const int b   = blockIdx.y;
    const int tid = threadIdx.x;
    const size_t row = ((size_t)b * C + c) * (size_t)S;
    const float* xr   = x + row;
    float*       orow = out + row;

    // Per-sample apply decision (uniform across the block -> no divergence).
    const bool apply = (mask[b] != 0);
    if (!apply) {
        const float4* xi = (const float4*)xr;
        float4*       oo = (float4*)orow;
        #pragma unroll
        for (int g = 0; g < S / 4 / NT; ++g)
            oo[g * NT + tid] = xi[g * NT + tid];
        return;
    }

    const float scl = scale[b];

    // ---- stage x into shared (permuted; scalar loads are fully coalesced,
    //      scalar stores hit banks at stride 3 -> conflict-free) ----
    #pragma unroll
    for (int g = 0; g < S / NT; ++g) {
        int i = g * NT + tid;
        sx[PERM(i)] = xr[i];
    }
    __syncthreads();

    // ---- spline second derivatives M via chunked two-pass IIR ----
    const float LAM = -0.26794919243112270647f;  // sqrt(3) - 2
    const float PL  =  0.26794919243112270647f;  // -LAM

    const int i0 = tid * CHUNK;
    float pv[CHUNK + W];

    // Fast path: all RHS reads are plain interior values.
    const bool fastpath = (i0 >= W + 3) && (i0 + CHUNK - 1 + W <= S - 4);

    if (fastpath) {
        float xm = sx[PERM(i0 - W - 1)];
        float xc = sx[PERM(i0 - W)];
        float p  = 0.f;
        #pragma unroll
        for (int k = 0; k < CHUNK + 2 * W; ++k) {
            float xp = sx[PERM(i0 - W + k + 1)];
            float r  = 6.f * (xm - 2.f * xc + xp);
            p = fmaf(LAM, p, r);
            if (k >= W) pv[k - W] = p;
            xm = xc; xc = xp;
        }
    } else {
        const float M1  = sx[PERM(0)]     - 2.f * sx[PERM(1)]     + sx[PERM(2)];
        const float MS2 = sx[PERM(S - 3)] - 2.f * sx[PERM(S - 2)] + sx[PERM(S - 1)];
        float p = 0.f;
        #pragma unroll
        for (int k = 0; k < CHUNK + 2 * W; ++k) {
            float r = rprime(sx, i0 - W + k, M1, MS2);
            p = fmaf(LAM, p, r);
            if (k >= W) pv[k - W] = p;
        }
    }

    // Backward (anticausal) pass, entirely in registers; write M to shared.
    {
        float q = 0.f;
        #pragma unroll
        for (int k = CHUNK + W - 1; k >= 0; --k) {
            q = fmaf(LAM, q, pv[k]);
            if (k < CHUNK) sm[PERM(i0 + k)] = PL * q;
        }
    }

    // Exact boundary M values (same-thread read-after-write on own chunk).
    if (tid == 0) {
        float M1 = sx[PERM(0)] - 2.f * sx[PERM(1)] + sx[PERM(2)];
        sm[PERM(1)] = M1;
        sm[PERM(0)] = 2.f * M1 - sm[PERM(2)];
    }
    if (tid == NT - 1) {
        float MS2 = sx[PERM(S - 3)] - 2.f * sx[PERM(S - 2)] + sx[PERM(S - 1)];
        sm[PERM(S - 2)] = MS2;
        sm[PERM(S - 1)] = 2.f * MS2 - sm[PERM(S - 3)];
    }
    __syncthreads();

    // ---- warped cubic evaluation, coalesced float4 stores ----
    #pragma unroll
    for (int g = 0; g < S / 4 / NT; ++g) {
        const int v  = g * NT + tid;
        const int s0 = v * 4;
        float4 o;
        float* op = (float*)&o;
        #pragma unroll
        for (int e = 0; e < 4; ++e) {
            float wv = fminf((float)(s0 + e) * scl, (float)(S - 1));
            int idx = (int)wv;            // wv >= 0 -> trunc == floor
            if (idx > S - 2) idx = S - 2;
            float tt = wv - (float)idx;
            float y0 = sx[PERM(idx)];
            float y1 = sx[PERM(idx + 1)];
            float m0 = sm[PERM(idx)];
            float m1 = sm[PERM(idx + 1)];
            float bb = (y1 - y0) - (2.f * m0 + m1) * (1.f / 6.f);
            float cc = 0.5f * m0;
            float dd = (m1 - m0) * (1.f / 6.f);
            op[e] = fmaf(tt, fmaf(tt, fmaf(tt, dd, cc), bb), y0);
        }
        ((float4*)orow)[v] = o;
    }
}

extern "C" void kernel_launch(void* const* d_in, const int* in_sizes, int n_in,
                              void* d_out, int out_size)
{
    const float* x     = (const float*)d_in[0];
    const float* scale = (const float*)d_in[1];
    const int*   mask  = (const int*)d_in[2];
    float*       out   = (float*)d_out;

    const int B = in_sizes[1];                 // 128
    const int C = in_sizes[0] / (B * S);       // 64

    dim3 grid(C, B);
    tw_kernel<<<grid, NT>>>(x, scale, mask, out, C);
}

// round 7
// speedup vs baseline: 1.0697x; 1.0393x over previous
#include <cuda_runtime.h>
#include <cuda_bf16.h>

// TIME_WARPING: per-row not-a-knot cubic spline fit + warped evaluation.
//
// Spline solve: interior tri(1,4,1) via causal+anticausal first-order IIR,
// lambda = sqrt(3)-2. Register-resident per-thread chunks (16 elems) with
// halos delivered by warp shuffles; boundary threads (0, NT-1) use the
// exact not-a-knot / method-of-images r' sequence with compile-time
// indices. Only ONE block barrier (before the warped-eval gather).
//
// Shared layout: XOR swizzle swz(i) = i ^ ((i>>5)&31). Conflict-free for
// lane-stride-16 stores (IIR phase) and ~stride-4 eval gathers.

#define S      4096
#define NT     256
#define CHUNK  16      // NT * CHUNK == S
#define W      8       // IIR warm-up length; |lambda|^8 ~ 2.7e-5

__device__ __forceinline__ int swz(int i) { return i ^ ((i >> 5) & 31); }

__global__ __launch_bounds__(NT)
void tw_kernel(const float* __restrict__ x,
               const float* __restrict__ scale,
               const int* __restrict__ mask,
               float* __restrict__ out, int C)
{
    __shared__ float sx[S];   // x row, swizzled
    __shared__ float sm[S];   // M row, swizzled

    const int c    = blockIdx.x;
    const int b    = blockIdx.y;
    const int tid  = threadIdx.x;
    const int lane = tid & 31;
    const size_t row = ((size_t)b * C + c) * (size_t)S;
    const float* xr   = x + row;
    float*       orow = out + row;

    // Uniform per-block decision -> no divergence.
    if (mask[b] == 0) {
        const float4* xi = (const float4*)xr;
        float4*       oo = (float4*)orow;
        #pragma unroll
        for (int g = 0; g < S / 4 / NT; ++g)
            oo[g * NT + tid] = xi[g * NT + tid];
        return;
    }

    const float scl = scale[b];
    const int   i0  = tid * CHUNK;

    // ---- load own chunk (coalesced LDG.128) into xa[9..24] ----
    float xa[34];                       // covers x[i0-9 .. i0+24]
    {
        const float4* xv = (const float4*)(xr + i0);
        float4 a0 = xv[0], a1 = xv[1], a2 = xv[2], a3 = xv[3];
        xa[9]  = a0.x; xa[10] = a0.y; xa[11] = a0.z; xa[12] = a0.w;
        xa[13] = a1.x; xa[14] = a1.y; xa[15] = a1.z; xa[16] = a1.w;
        xa[17] = a2.x; xa[18] = a2.y; xa[19] = a2.z; xa[20] = a2.w;
        xa[21] = a3.x; xa[22] = a3.y; xa[23] = a3.z; xa[24] = a3.w;
    }

    // Stage x to shared early (conflict-free: lane stride 16 under swz).
    #pragma unroll
    for (int q = 0; q < CHUNK; ++q)
        sx[swz(i0 + q)] = xa[9 + q];

    // ---- halos via warp shuffle (not an L1-datapath consumer) ----
    #pragma unroll
    for (int q = 0; q < 9; ++q)
        xa[q] = __shfl_up_sync(0xffffffffu, xa[16 + q], 1);
    #pragma unroll
    for (int q = 0; q < 9; ++q)
        xa[25 + q] = __shfl_down_sync(0xffffffffu, xa[9 + q], 1);
    // warp-edge lanes patch from global (few sectors, L1-hot)
    if (lane == 0 && tid != 0) {
        #pragma unroll
        for (int q = 0; q < 9; ++q) xa[q] = xr[i0 - 9 + q];
    }
    if (lane == 31 && tid != NT - 1) {
        #pragma unroll
        for (int q = 0; q < 9; ++q) xa[25 + q] = xr[i0 + 16 + q];
    }

    // Boundary constants (cheap; only meaningful on tid 0 / NT-1).
    const float M1  = xa[9]  - 2.f * xa[10] + xa[11];   // tid 0:   x0-2x1+x2
    const float MS2 = xa[22] - 2.f * xa[23] + xa[24];   // tid 255: exact M_{S-2}

    // ---- forward (causal) pass, registers only ----
    const float LAM     = -0.26794919243112270647f;  // sqrt(3)-2
    const float PL      =  0.26794919243112270647f;
    const float INV1ML2 =  1.07735026918962576451f;  // 1/(1-lambda^2)
    const float LP[8] = { 1.f, -0.26794919243112270647f, 0.07179676972449082073f,
                          -0.01923788646684063666f, 0.00515470534915383427f,
                          -0.00138119963856238452f, 0.00037009153465686223f,
                          -0.00009916538111266178f };

    float pv[CHUNK];
    float p = 0.f, A = 0.f;

    #pragma unroll
    for (int k = 0; k < CHUNK + 2 * W; ++k) {          // j = i0 - 8 + k
        float r = 6.f * (xa[k] - 2.f * xa[k + 1] + xa[k + 2]);

        // tid 0: exact not-a-knot left end (images about node 1)
        if (tid == 0) {
            if (k <= 7)       r = -6.f * (xa[18 - k] - 2.f * xa[19 - k] + xa[20 - k]);
            else if (k == 8)  r = -(6.f * (xa[10] - 2.f * xa[11] + xa[12]) - M1);
            else if (k == 9)  r = 0.f;
            else if (k == 10) r = 6.f * (xa[10] - 2.f * xa[11] + xa[12]) - M1;
        }
        // tid NT-1: exact right end (images about node S-2)
        if (tid == NT - 1) {
            if (k == 21)      r = 6.f * (xa[21] - 2.f * xa[22] + xa[23]) - MS2;
            else if (k == 22) r = 0.f;
            else if (k == 23) r = -(6.f * (xa[21] - 2.f * xa[22] + xa[23]) - MS2);
            else if (k >= 24) r = -6.f * (xa[44 - k] - 2.f * xa[45 - k] + xa[46 - k]);
        }

        if (k < CHUNK + W) {
            p = fmaf(LAM, p, r);
            if (k >= W) pv[k - W] = p;
        } else {
            A = fmaf(LP[k - (CHUNK + W)], r, A);
        }
    }

    // ---- backward (anticausal) pass; analytic seed q_16 ----
    float mcap2 = 0.f, mcap13 = 0.f;
    {
        float q = (fmaf(LAM, pv[CHUNK - 1], A)) * INV1ML2;
        #pragma unroll
        for (int k = CHUNK - 1; k >= 0; --k) {
            q = fmaf(LAM, q, pv[k]);
            float u = PL * q;                 // M_{i0+k}
            sm[swz(i0 + k)] = u;
            if (k == 2)  mcap2  = u;
            if (k == 13) mcap13 = u;
        }
    }

    // Exact boundary M overrides (same-thread smem ordering).
    if (tid == 0) {
        sm[swz(1)] = M1;
        sm[swz(0)] = 2.f * M1 - mcap2;        // M0 = 2*M1 - M2
    }
    if (tid == NT - 1) {
        sm[swz(S - 2)] = MS2;
        sm[swz(S - 1)] = 2.f * MS2 - mcap13;  // M_{S-1} = 2*M_{S-2} - M_{S-3}
    }

    __syncthreads();   // the ONLY barrier: sx + sm ready for the gather

    // ---- warped cubic evaluation, coalesced float4 stores ----
    #pragma unroll
    for (int g = 0; g < S / 4 / NT; ++g) {
        const int v  = g * NT + tid;
        const int s0 = v * 4;
        float4 o;
        float* op = (float*)&o;
        #pragma unroll
        for (int e = 0; e < 4; ++e) {
            float wv = fminf((float)(s0 + e) * scl, (float)(S - 1));
            int idx = (int)wv;                // wv >= 0 -> trunc == floor
            if (idx > S - 2) idx = S - 2;
            float tt = wv - (float)idx;
            int a0 = swz(idx);
            int a1 = swz(idx + 1);
            float y0 = sx[a0];
            float y1 = sx[a1];
            float m0 = sm[a0];
            float m1 = sm[a1];
            float bb = (y1 - y0) - (2.f * m0 + m1) * (1.f / 6.f);
            float cc = 0.5f * m0;
            float dd = (m1 - m0) * (1.f / 6.f);
            op[e] = fmaf(tt, fmaf(tt, fmaf(tt, dd, cc), bb), y0);
        }
        ((float4*)orow)[v] = o;
    }
}

extern "C" void kernel_launch(void* const* d_in, const int* in_sizes, int n_in,
                              void* d_out, int out_size)
{
    const float* x     = (const float*)d_in[0];
    const float* scale = (const float*)d_in[1];
    const int*   mask  = (const int*)d_in[2];
    float*       out   = (float*)d_out;

    const int B = in_sizes[1];                 // 128
    const int C = in_sizes[0] / (B * S);       // 64

    dim3 grid(C, B);
    tw_kernel<<<grid, NT>>>(x, scale, mask, out, C);
}

// round 8
// speedup vs baseline: 1.2471x; 1.1658x over previous
#include <cuda_runtime.h>
#include <cuda_fp16.h>

// TIME_WARPING: not-a-knot cubic spline fit + warped evaluation.
// IIR spline solve (lambda = sqrt(3)-2) fully register-resident with
// shuffle halos; per-interval coefficients packed as 4 x fp16 = 8 bytes
// (y0, y1, M0, M1) into ONE shared uint2 array -> eval is a single LDS.64.

#define S      4096
#define NT     256
#define CHUNK  16
#define W      8

#define LAM     (-0.26794919243112270647f)
#define PL      ( 0.26794919243112270647f)
#define INV1ML2 ( 1.07735026918962576451f)

__device__ __forceinline__ int pswz(int i) { return i ^ ((i >> 4) & 15); }

__device__ __forceinline__ void pstore(uint2* spk, int i,
                                       float y0, float y1, float m0, float m1)
{
    __half2 hy = __floats2half2_rn(y0, y1);
    __half2 hm = __floats2half2_rn(m0, m1);
    uint2 v;
    v.x = *reinterpret_cast<unsigned*>(&hy);
    v.y = *reinterpret_cast<unsigned*>(&hm);
    spk[pswz(i)] = v;
}

// MODE 0: interior thread. MODE 1: tid 0 (left not-a-knot images).
// MODE 2: tid NT-1 (right images). xa[m] = x[i0 - 9 + m], m in [0,34).
template<int MODE>
__device__ __forceinline__ void solve_and_pack(const float* xa, uint2* spk,
                                               int i0, float M1, float MS2)
{
    const float LP[8] = { 1.f, -0.26794919243112270647f, 0.07179676972449082073f,
                          -0.01923788646684063666f, 0.00515470534915383427f,
                          -0.00138119963856238452f, 0.00037009153465686223f,
                          -0.00009916538111266178f };
    float pv[CHUNK];
    float p = 0.f, A = 0.f;

#define RR(m) (6.f * (xa[(m)] - 2.f * xa[(m) + 1] + xa[(m) + 2]))

    #pragma unroll
    for (int k = 0; k < CHUNK + 2 * W; ++k) {        // j = i0 - 8 + k
        float r;
        if (MODE == 1) {
            if (k <= 7)       r = -RR(18 - k);
            else if (k == 8)  r = -(RR(10) - M1);
            else if (k == 9)  r = 0.f;
            else if (k == 10) r = RR(10) - M1;
            else              r = RR(k);
        } else if (MODE == 2) {
            if (k == 21)      r = RR(21) - MS2;
            else if (k == 22) r = 0.f;
            else if (k == 23) r = -(RR(21) - MS2);
            else if (k >= 24) r = -RR(44 - k);
            else              r = RR(k);
        } else {
            r = RR(k);
        }
        if (k < CHUNK + W) {
            p = fmaf(LAM, p, r);
            if (k >= W) pv[k - W] = p;
        } else {
            A = fmaf(LP[k - (CHUNK + W)], r, A);
        }
    }
#undef RR

    // Backward pass fused with coefficient packing.
    float q      = fmaf(LAM, pv[CHUNK - 1], A) * INV1ML2;  // q_{16}
    float u_next = PL * q;                                  // M_{i0+16}
    float u13    = 0.f, u2 = 0.f;

    #pragma unroll
    for (int k = CHUNK - 1; k >= 0; --k) {
        q = fmaf(LAM, q, pv[k]);
        float u = PL * q;                                   // M_{i0+k}

        if (MODE == 1) {
            if (k == 2) u2 = u;
            if (k == 1) u = M1;                             // exact M1
            if (k == 0) u = 2.f * M1 - u2;                  // M0 = 2M1 - M2
        }
        if (MODE == 2) {
            if (k == 14) u = MS2;                           // exact M_{S-2}
            if (k == 15) { u_next = u; continue; }          // interval S-1 unused
            if (k == 14) { u_next = u; continue; }          // deferred to k==13
            if (k == 13) {
                u13 = u;
                // interval S-2 = i0+14: (y, y, M_{S-2}, M_{S-1})
                pstore(spk, i0 + 14, xa[23], xa[24], MS2, 2.f * MS2 - u13);
            }
        }

        pstore(spk, i0 + k, xa[9 + k], xa[10 + k], u, u_next);
        u_next = u;
    }
}

__global__ __launch_bounds__(NT)
void tw_kernel(const float* __restrict__ x,
               const float* __restrict__ scale,
               const int* __restrict__ mask,
               float* __restrict__ out, int C)
{
    __shared__ uint2 spk[S];    // packed (y0, y1, M0, M1) fp16x4 per interval

    const int c    = blockIdx.x;
    const int b    = blockIdx.y;
    const int tid  = threadIdx.x;
    const int lane = tid & 31;
    const size_t row = ((size_t)b * C + c) * (size_t)S;
    const float* xr   = x + row;
    float*       orow = out + row;

    if (mask[b] == 0) {                         // uniform per block
        const float4* xi = (const float4*)xr;
        float4*       oo = (float4*)orow;
        #pragma unroll
        for (int g = 0; g < S / 4 / NT; ++g)
            oo[g * NT + tid] = xi[g * NT + tid];
        return;
    }

    const float scl = scale[b];
    const int   i0  = tid * CHUNK;

    // Own chunk: 4x LDG.128 -> xa[9..24]
    float xa[34];
    {
        const float4* xv = (const float4*)(xr + i0);
        float4 a0 = xv[0], a1 = xv[1], a2 = xv[2], a3 = xv[3];
        xa[9]  = a0.x; xa[10] = a0.y; xa[11] = a0.z; xa[12] = a0.w;
        xa[13] = a1.x; xa[14] = a1.y; xa[15] = a1.z; xa[16] = a1.w;
        xa[17] = a2.x; xa[18] = a2.y; xa[19] = a2.z; xa[20] = a2.w;
        xa[21] = a3.x; xa[22] = a3.y; xa[23] = a3.z; xa[24] = a3.w;
    }

    // Halos via warp shuffle; warp-edge lanes patch from global.
    #pragma unroll
    for (int q = 0; q < 9; ++q)
        xa[q] = __shfl_up_sync(0xffffffffu, xa[16 + q], 1);
    #pragma unroll
    for (int q = 0; q < 9; ++q)
        xa[25 + q] = __shfl_down_sync(0xffffffffu, xa[9 + q], 1);
    if (lane == 0 && tid != 0) {
        #pragma unroll
        for (int q = 0; q < 9; ++q) xa[q] = xr[i0 - 9 + q];
    }
    if (lane == 31 && tid != NT - 1) {
        #pragma unroll
        for (int q = 0; q < 9; ++q) xa[25 + q] = xr[i0 + 16 + q];
    }

    const float M1  = xa[9]  - 2.f * xa[10] + xa[11];   // tid 0
    const float MS2 = xa[22] - 2.f * xa[23] + xa[24];   // tid NT-1

    if (tid == 0)            solve_and_pack<1>(xa, spk, i0, M1, MS2);
    else if (tid == NT - 1)  solve_and_pack<2>(xa, spk, i0, M1, MS2);
    else                     solve_and_pack<0>(xa, spk, i0, M1, MS2);

    __syncthreads();

    // Warped cubic evaluation: ONE LDS.64 per element.
    #pragma unroll
    for (int g = 0; g < S / 4 / NT; ++g) {
        const int v  = g * NT + tid;
        const int s0 = v * 4;
        float4 o;
        float* op = (float*)&o;
        #pragma unroll
        for (int e = 0; e < 4; ++e) {
            float wv = fminf((float)(s0 + e) * scl, (float)(S - 1));
            int idx = (int)wv;
            if (idx > S - 2) idx = S - 2;
            float tt = wv - (float)idx;

            uint2 pk = spk[pswz(idx)];
            __half2 hy = *reinterpret_cast<__half2*>(&pk.x);
            __half2 hm = *reinterpret_cast<__half2*>(&pk.y);
            float2 yy = __half22float2(hy);
            float2 mm = __half22float2(hm);

            float bb = (yy.y - yy.x) - (2.f * mm.x + mm.y) * (1.f / 6.f);
            float cc = 0.5f * mm.x;
            float dd = (mm.y - mm.x) * (1.f / 6.f);
            op[e] = fmaf(tt, fmaf(tt, fmaf(tt, dd, cc), bb), yy.x);
        }
        ((float4*)orow)[v] = o;
    }
}

extern "C" void kernel_launch(void* const* d_in, const int* in_sizes, int n_in,
                              void* d_out, int out_size)
{
    const float* x     = (const float*)d_in[0];
    const float* scale = (const float*)d_in[1];
    const int*   mask  = (const int*)d_in[2];
    float*       out   = (float*)d_out;

    const int B = in_sizes[1];
    const int C = in_sizes[0] / (B * S);

    dim3 grid(C, B);
    tw_kernel<<<grid, NT>>>(x, scale, mask, out, C);
}

// round 9
// speedup vs baseline: 1.2991x; 1.0417x over previous
#include <cuda_runtime.h>
#include <cuda_fp16.h>

// TIME_WARPING: not-a-knot cubic spline fit + warped evaluation.
// IIR spline solve (lambda = sqrt(3)-2) fully register-resident with
// shuffle halos; per-interval coefficients packed as 4 x fp16 = 8 bytes
// (y0, y1, M0, M1) into ONE shared uint2 array -> eval is a single LDS.64.
// Eval uses stride-1 lane mapping (one output/thread/iter) so the gather
// is near conflict-free; stores are scalar but lane-coalesced.

#define S      4096
#define NT     256
#define CHUNK  16
#define W      6       // warm-up; |lambda|^6 ~ 3.7e-4 -> ~1e-4 output rel

#define LAM     (-0.26794919243112270647f)
#define PL      ( 0.26794919243112270647f)
#define INV1ML2 ( 1.07735026918962576451f)

__device__ __forceinline__ int pswz(int i) { return i ^ ((i >> 4) & 15); }

__device__ __forceinline__ void pstore(uint2* spk, int i,
                                       float y0, float y1, float m0, float m1)
{
    __half2 hy = __floats2half2_rn(y0, y1);
    __half2 hm = __floats2half2_rn(m0, m1);
    uint2 v;
    v.x = *reinterpret_cast<unsigned*>(&hy);
    v.y = *reinterpret_cast<unsigned*>(&hm);
    spk[pswz(i)] = v;
}

// xa[m] = x[i0 - 7 + m], m in [0, 30).  y_{i0+k} = xa[7+k].
// MODE 0: interior. MODE 1: tid 0 (left not-a-knot images about node 1).
// MODE 2: tid NT-1 (right images about node S-2).
template<int MODE>
__device__ __forceinline__ void solve_and_pack(const float* xa, uint2* spk,
                                               int i0, float M1, float MS2)
{
    const float LP[6] = { 1.f, -0.26794919243112270647f, 0.07179676972449082073f,
                          -0.01923788646684063666f, 0.00515470534915383427f,
                          -0.00138119963856238452f };
    float pv[CHUNK];
    float p = 0.f, A = 0.f;

#define RR(m) (6.f * (xa[(m)] - 2.f * xa[(m) + 1] + xa[(m) + 2]))

    #pragma unroll
    for (int k = 0; k < CHUNK + 2 * W; ++k) {        // j = i0 - 6 + k
        float r;
        if (MODE == 1) {
            // j = k - 6
            if (k <= 5)       r = -RR(14 - k);        // j<0: -r(2-j)
            else if (k == 6)  r = -(RR(8) - M1);      // j=0: image of j=2
            else if (k == 7)  r = 0.f;                // j=1: Dirichlet
            else if (k == 8)  r = RR(8) - M1;         // j=2
            else              r = RR(k);
        } else if (MODE == 2) {
            // j = 4074 + k  (i0 = 4080)
            if (k == 19)      r = RR(19) - MS2;       // j = S-3
            else if (k == 20) r = 0.f;                // j = S-2
            else if (k == 21) r = -(RR(19) - MS2);    // j = S-1 mirrors S-3
            else if (k >= 22) r = -RR(46 - k);        // j>S-1: -r(2(S-2)-j)
            else              r = RR(k);
        } else {
            r = RR(k);
        }
        if (k < CHUNK + W) {
            p = fmaf(LAM, p, r);
            if (k >= W) pv[k - W] = p;
        } else {
            A = fmaf(LP[k - (CHUNK + W)], r, A);
        }
    }
#undef RR

    // Backward pass fused with packing. q_16 seeded analytically.
    float q      = fmaf(LAM, pv[CHUNK - 1], A) * INV1ML2;
    float u_next = PL * q;                   // M_{i0+16} (unused in MODE 2)
    float u2     = 0.f;

    #pragma unroll
    for (int k = CHUNK - 1; k >= 0; --k) {
        q = fmaf(LAM, q, pv[k]);
        float u = PL * q;                    // M_{i0+k}

        if (MODE == 1) {
            if (k == 2) u2 = u;
            if (k == 1) u = M1;              // exact M1
            if (k == 0) u = 2.f * M1 - u2;   // M0 = 2*M1 - M2
        }
        if (MODE == 2) {
            if (k == 15) { u_next = 0.f; continue; }   // interval S-1 unused
            if (k == 14) { u_next = MS2; continue; }   // store deferred
            if (k == 13) {
                // interval S-2 = i0+14: (y_{S-2}, y_{S-1}, MS2, M_{S-1})
                pstore(spk, i0 + 14, xa[21], xa[22], MS2, 2.f * MS2 - u);
                // fall through: generic store of interval i0+13 with
                // (u13, u_next = MS2)
            }
        }

        pstore(spk, i0 + k, xa[7 + k], xa[8 + k], u, u_next);
        u_next = u;
    }
}

__global__ __launch_bounds__(NT)
void tw_kernel(const float* __restrict__ x,
               const float* __restrict__ scale,
               const int* __restrict__ mask,
               float* __restrict__ out, int C)
{
    __shared__ uint2 spk[S];    // packed (y0, y1, M0, M1) fp16x4 per interval

    const int c    = blockIdx.x;
    const int b    = blockIdx.y;
    const int tid  = threadIdx.x;
    const int lane = tid & 31;
    const size_t row = ((size_t)b * C + c) * (size_t)S;
    const float* xr   = x + row;
    float*       orow = out + row;

    if (mask[b] == 0) {                      // uniform per block
        const float4* xi = (const float4*)xr;
        float4*       oo = (float4*)orow;
        #pragma unroll
        for (int g = 0; g < S / 4 / NT; ++g)
            oo[g * NT + tid] = xi[g * NT + tid];
        return;
    }

    const float scl = scale[b];
    const int   i0  = tid * CHUNK;

    // Own chunk: 4x LDG.128 -> xa[7..22]
    float xa[30];
    {
        const float4* xv = (const float4*)(xr + i0);
        float4 a0 = xv[0], a1 = xv[1], a2 = xv[2], a3 = xv[3];
        xa[7]  = a0.x; xa[8]  = a0.y; xa[9]  = a0.z; xa[10] = a0.w;
        xa[11] = a1.x; xa[12] = a1.y; xa[13] = a1.z; xa[14] = a1.w;
        xa[15] = a2.x; xa[16] = a2.y; xa[17] = a2.z; xa[18] = a2.w;
        xa[19] = a3.x; xa[20] = a3.y; xa[21] = a3.z; xa[22] = a3.w;
    }

    // Halos via warp shuffle; warp-edge lanes patch from global.
    #pragma unroll
    for (int q = 0; q < 7; ++q)
        xa[q] = __shfl_up_sync(0xffffffffu, xa[16 + q], 1);
    #pragma unroll
    for (int q = 0; q < 7; ++q)
        xa[23 + q] = __shfl_down_sync(0xffffffffu, xa[7 + q], 1);
    if (lane == 0 && tid != 0) {
        #pragma unroll
        for (int q = 0; q < 7; ++q) xa[q] = xr[i0 - 7 + q];
    }
    if (lane == 31 && tid != NT - 1) {
        #pragma unroll
        for (int q = 0; q < 7; ++q) xa[23 + q] = xr[i0 + 16 + q];
    }

    const float M1  = xa[7]  - 2.f * xa[8]  + xa[9];    // tid 0:   x0-2x1+x2
    const float MS2 = xa[20] - 2.f * xa[21] + xa[22];   // tid NT-1: M_{S-2}

    if (tid == 0)            solve_and_pack<1>(xa, spk, i0, M1, MS2);
    else if (tid == NT - 1)  solve_and_pack<2>(xa, spk, i0, M1, MS2);
    else                     solve_and_pack<0>(xa, spk, i0, M1, MS2);

    __syncthreads();

    // Warped cubic evaluation, stride-1 lane mapping: adjacent lanes read
    // adjacent (or identical -> broadcast) intervals; scalar coalesced STG.
    #pragma unroll
    for (int g = 0; g < S / NT; ++g) {
        const int v = g * NT + tid;
        float wv = fminf((float)v * scl, (float)(S - 1));
        int idx = (int)wv;
        if (idx > S - 2) idx = S - 2;
        float tt = wv - (float)idx;

        uint2 pk = spk[pswz(idx)];
        __half2 hy = *reinterpret_cast<__half2*>(&pk.x);
        __half2 hm = *reinterpret_cast<__half2*>(&pk.y);
        float2 yy = __half22float2(hy);
        float2 mm = __half22float2(hm);

        float bb = (yy.y - yy.x) - (2.f * mm.x + mm.y) * (1.f / 6.f);
        float cc = 0.5f * mm.x;
        float dd = (mm.y - mm.x) * (1.f / 6.f);
        orow[v] = fmaf(tt, fmaf(tt, fmaf(tt, dd, cc), bb), yy.x);
    }
}

extern "C" void kernel_launch(void* const* d_in, const int* in_sizes, int n_in,
                              void* d_out, int out_size)
{
    const float* x     = (const float*)d_in[0];
    const float* scale = (const float*)d_in[1];
    const int*   mask  = (const int*)d_in[2];
    float*       out   = (float*)d_out;

    const int B = in_sizes[1];
    const int C = in_sizes[0] / (B * S);

    dim3 grid(C, B);
    tw_kernel<<<grid, NT>>>(x, scale, mask, out, C);
}